// round 15
// baseline (speedup 1.0000x reference)
#include <cuda_runtime.h>
#include <cuda_fp16.h>
#include <mma.h>
#include <cstdint>
#include <math.h>

using namespace nvcuda;

// Problem constants (B=2, S=2048, H=1024, E=8, I=4096, top-2)
#define NT 4096
#define HD 1024
#define NE 8
#define ID 4096
#define NSLOT (2 * NT)

// GEMM tiling: CTA 128x128, 8 warps, warp 32x64, BK=64 (fp16), 3-stage cp.async
#define TM 128
#define TN 128
#define BK 64
#define LDA 72            // As leading dim (halfs); row stride 144B
#define LDB 136           // Bs leading dim (halfs); row stride 272B
#define RTILES 32         // NT / TM

#define ASZ (TM * LDA)            // 9216 halfs
#define BSZ (BK * LDB)            // 8704 halfs
#define STAGE_H (ASZ + BSZ)       // 17920 halfs
#define STAGE_B (STAGE_H * 2)     // 35840 bytes
#define ASZB (ASZ * 2)            // 18432 bytes
#define NSTAGE 3
#define SMEM_BYTES (NSTAGE * STAGE_B)   // 107520

// ---------------- static device scratch (no runtime alloc) ----------------
__device__ int    g_counts[NE];
__device__ int    g_offsets[NE + 1];
__device__ int    g_tok[NE * NT];
__device__ int    g_meta_i[NT * 4];
__device__ float  g_meta_w[NT * 2];
__device__ __half g_hdn[(size_t)NSLOT * ID];   // fp16 silu(x@W1) rows (compacted)
__device__ float  g_y[(size_t)NSLOT * HD];
// fp16 operand copies
__device__ __half g_xh[(size_t)NT * HD];
__device__ __half g_w1h[(size_t)NE * HD * ID];
__device__ __half g_w2h[(size_t)NE * ID * HD];

// ---------------- helpers ----------------
__device__ __forceinline__ uint32_t smem_u32(const void* p) {
    uint32_t a;
    asm("{ .reg .u64 t; cvta.to.shared.u64 t, %1; cvt.u32.u64 %0, t; }" : "=r"(a) : "l"(p));
    return a;
}
// 16B async copy; bytes==0 -> zero-fill destination
__device__ __forceinline__ void cp16(uint32_t dst, const void* src, uint32_t bytes) {
    asm volatile("cp.async.cg.shared.global [%0], [%1], 16, %2;"
                 :: "r"(dst), "l"(src), "r"(bytes) : "memory");
}
#define CP_COMMIT() asm volatile("cp.async.commit_group;" ::: "memory")

struct __align__(8) h4 { __half2 a, b; };

// ---------------- gate / prefix ----------------
__global__ void gate_kernel(const float* __restrict__ x, const float* __restrict__ Wg) {
    int warp = (blockIdx.x * blockDim.x + threadIdx.x) >> 5;
    int lane = threadIdx.x & 31;
    if (warp >= NT) return;
    const float* xr = x + (size_t)warp * HD;

    float acc[NE];
#pragma unroll
    for (int i = 0; i < NE; i++) acc[i] = 0.f;
    for (int j = lane; j < HD; j += 32) {
        float xv = xr[j];
        const float4* w4 = reinterpret_cast<const float4*>(Wg + j * NE);
        float4 wa = w4[0], wb = w4[1];
        acc[0] += xv * wa.x; acc[1] += xv * wa.y;
        acc[2] += xv * wa.z; acc[3] += xv * wa.w;
        acc[4] += xv * wb.x; acc[5] += xv * wb.y;
        acc[6] += xv * wb.z; acc[7] += xv * wb.w;
    }
#pragma unroll
    for (int i = 0; i < NE; i++) {
#pragma unroll
        for (int o = 16; o > 0; o >>= 1)
            acc[i] += __shfl_xor_sync(0xffffffffu, acc[i], o);
    }
    if (lane == 0) {
        int i0 = 0; float m0 = acc[0];
#pragma unroll
        for (int i = 1; i < NE; i++) if (acc[i] > m0) { m0 = acc[i]; i0 = i; }
        int i1 = -1; float m1 = -1e30f;
#pragma unroll
        for (int i = 0; i < NE; i++)
            if (i != i0 && acc[i] > m1) { m1 = acc[i]; i1 = i; }
        float w0 = 1.f / (1.f + expf(m1 - m0));
        float w1 = 1.f - w0;
        int s0 = atomicAdd(&g_counts[i0], 1);
        int s1 = atomicAdd(&g_counts[i1], 1);
        g_tok[i0 * NT + s0] = warp;
        g_tok[i1 * NT + s1] = warp;
        g_meta_i[warp * 4 + 0] = i0;
        g_meta_i[warp * 4 + 1] = s0;
        g_meta_i[warp * 4 + 2] = i1;
        g_meta_i[warp * 4 + 3] = s1;
        g_meta_w[warp * 2 + 0] = w0;
        g_meta_w[warp * 2 + 1] = w1;
    }
}

__global__ void prefix_kernel() {
    if (threadIdx.x == 0) {
        int s = 0;
        g_offsets[0] = 0;
        for (int e = 0; e < NE; e++) { s += g_counts[e]; g_offsets[e + 1] = s; }
    }
}

// ---------------- fused reset + fp32->fp16 convert (x, W1, W2) ----------------
// Runs FIRST; gate (which atomics g_counts) launches after it in stream order.
__global__ void conv3_kernel(const float4* __restrict__ s0, h4* __restrict__ d0, int n0,
                             const float4* __restrict__ s1, h4* __restrict__ d1, int n1,
                             const float4* __restrict__ s2, h4* __restrict__ d2, int n2)
{
    if (blockIdx.x == 0 && threadIdx.x < NE) g_counts[threadIdx.x] = 0;

    int total = n0 + n1 + n2;
    int stride = gridDim.x * blockDim.x;
    for (int i = blockIdx.x * blockDim.x + threadIdx.x; i < total; i += stride) {
        if (i < n0) {
            float4 v = s0[i];
            h4 o; o.a = __floats2half2_rn(v.x, v.y); o.b = __floats2half2_rn(v.z, v.w);
            d0[i] = o;
        } else if (i < n0 + n1) {
            int k = i - n0;
            float4 v = s1[k];
            h4 o; o.a = __floats2half2_rn(v.x, v.y); o.b = __floats2half2_rn(v.z, v.w);
            d1[k] = o;
        } else {
            int k = i - n0 - n1;
            float4 v = s2[k];
            h4 o; o.a = __floats2half2_rn(v.x, v.y); o.b = __floats2half2_rn(v.z, v.w);
            d2[k] = o;
        }
    }
}

// ---------------- grouped GEMM (MODE 0 = up+SiLU, 1 = down), fp16 MMA ----------------
template <int MODE>
__global__ __launch_bounds__(256, 2) void gemm_tc(
    const __half* __restrict__ A, const __half* __restrict__ W,
    const float* __restrict__ bias)
{
    extern __shared__ __align__(16) char smem[];
    __half* sh = reinterpret_cast<__half*>(smem);
    const int KS  = (MODE == 0) ? HD : ID;   // K extent (A row length)
    const int NSW = (MODE == 0) ? ID : HD;   // W row length (N extent)
    const int KT  = KS / BK;                 // 16 (up) / 64 (down)

    int e  = blockIdx.x / RTILES;
    int rt = blockIdx.x % RTILES;
    int n_e = g_counts[e];
    int row0 = rt * TM;
    if (row0 >= n_e) return;
    int n0 = blockIdx.y * TN;
    int tid = threadIdx.x;
    uint32_t sb = smem_u32(sh);

    // A staging: 2 threads per row; each stages 64B (32 halfs) of the 128B row
    const __half* aptr = nullptr;
    {
        int gs = row0 + (tid >> 1);
        if (gs < n_e) {
            if (MODE == 0) aptr = A + (size_t)g_tok[e * NT + gs] * HD;
            else           aptr = A + (size_t)(g_offsets[e] + gs) * ID;
        }
    }
    int ahalf = tid & 1;
    uint32_t a_dst = sb + (tid >> 1) * 144 + ahalf * 64;
    uint32_t avalid = aptr ? 16u : 0u;
    const __half* adummy = W;

    // B staging: 4 threads per row (64 rows); each stages 64B of the 256B row
    int brow = tid >> 2, bseg = tid & 3;
    const __half* wbase = W + (size_t)e * HD * ID
                            + (size_t)brow * NSW + n0 + bseg * 32;
    uint32_t b_dst = sb + ASZB + brow * 272 + bseg * 64;

    auto issue = [&](int kt) {
        uint32_t so = (uint32_t)((kt % NSTAGE) * STAGE_B);
        int k0 = kt * BK;
        const __half* as = aptr ? (aptr + k0 + ahalf * 32) : adummy;
#pragma unroll
        for (int g = 0; g < 4; ++g)
            cp16(a_dst + so + g * 16, as + g * 8, avalid);
        const __half* bs = wbase + (size_t)k0 * NSW;
#pragma unroll
        for (int g = 0; g < 4; ++g)
            cp16(b_dst + so + g * 16, bs + g * 8, 16u);
        CP_COMMIT();
    };

    int wrp = tid >> 5, wm = wrp >> 1, wn = wrp & 1, lane = tid & 31;

    wmma::fragment<wmma::accumulator, 16, 16, 16, float> c[2][4];
#pragma unroll
    for (int i = 0; i < 2; i++)
#pragma unroll
        for (int j = 0; j < 4; j++) wmma::fill_fragment(c[i][j], 0.f);

    issue(0);
    if (KT > 1) issue(1);

    for (int kt = 0; kt < KT; ++kt) {
        if (kt + 1 < KT) asm volatile("cp.async.wait_group 1;" ::: "memory");
        else             asm volatile("cp.async.wait_group 0;" ::: "memory");
        __syncthreads();                 // stage kt visible; stage (kt-1)%3 readers retired
        if (kt + 2 < KT) issue(kt + 2);  // writes stage (kt-1)%3 (safe)

        const __half* As = sh + (size_t)(kt % NSTAGE) * STAGE_H;
        const __half* Bs = As + ASZ;
#pragma unroll
        for (int kk = 0; kk < 4; ++kk) {    // four k16 steps per BK=64 slice
            wmma::fragment<wmma::matrix_a, 16, 16, 16, half, wmma::row_major> af[2];
            wmma::fragment<wmma::matrix_b, 16, 16, 16, half, wmma::row_major> bf[4];
#pragma unroll
            for (int i = 0; i < 2; i++)
                wmma::load_matrix_sync(af[i], &As[(wm * 32 + i * 16) * LDA + kk * 16], LDA);
#pragma unroll
            for (int j = 0; j < 4; j++)
                wmma::load_matrix_sync(bf[j], &Bs[(kk * 16) * LDB + wn * 64 + j * 16], LDB);
#pragma unroll
            for (int i = 0; i < 2; i++)
#pragma unroll
                for (int j = 0; j < 4; j++)
                    wmma::mma_sync(c[i][j], af[i], bf[j], c[i][j]);
        }
    }
    __syncthreads();   // all MMAs done; stage smem reusable as epilogue patch

    int base_row = g_offsets[e] + row0;
    float* patch = reinterpret_cast<float*>(smem) + wrp * 320;   // 16x20 floats per warp
#pragma unroll
    for (int i = 0; i < 2; i++) {
#pragma unroll
        for (int j = 0; j < 4; j++) {
            wmma::store_matrix_sync(patch, c[i][j], 20, wmma::mem_row_major);
            __syncwarp();
            int lrb = wm * 32 + i * 16;
            int lcb = wn * 64 + j * 16;
#pragma unroll
            for (int q = 0; q < 8; q++) {
                int el = lane + q * 32;
                int r = el >> 4, cc = el & 15;
                int lr = lrb + r;
                if (row0 + lr < n_e) {
                    int gc = n0 + lcb + cc;
                    if (MODE == 0) {
                        float v = patch[r * 20 + cc] + bias[(size_t)e * ID + gc];
                        float sv = v / (1.f + expf(-v));
                        g_hdn[(size_t)(base_row + lr) * ID + gc] = __float2half_rn(sv);
                    } else {
                        g_y[(size_t)(base_row + lr) * HD + gc] = patch[r * 20 + cc];
                    }
                }
            }
            __syncwarp();
        }
    }
}

// ---------------- deterministic per-token combine ----------------
__global__ void combine_kernel(const float* __restrict__ b2, float* __restrict__ out) {
    int t = blockIdx.x;
    int e0 = g_meta_i[t * 4 + 0], s0 = g_meta_i[t * 4 + 1];
    int e1 = g_meta_i[t * 4 + 2], s1 = g_meta_i[t * 4 + 3];
    float w0 = g_meta_w[t * 2 + 0];
    float w1 = g_meta_w[t * 2 + 1];
    int r0 = g_offsets[e0] + s0;
    int r1 = g_offsets[e1] + s1;

    const float4* y0 = reinterpret_cast<const float4*>(g_y + (size_t)r0 * HD);
    const float4* y1 = reinterpret_cast<const float4*>(g_y + (size_t)r1 * HD);
    const float4* c0 = reinterpret_cast<const float4*>(b2 + (size_t)e0 * HD);
    const float4* c1 = reinterpret_cast<const float4*>(b2 + (size_t)e1 * HD);
    float4* o = reinterpret_cast<float4*>(out + (size_t)t * HD);

    int h = threadIdx.x;  // blockDim = 256 == HD/4
    float4 a = y0[h], b = y1[h], p = c0[h], q = c1[h];
    float4 rr;
    rr.x = w0 * (a.x + p.x) + w1 * (b.x + q.x);
    rr.y = w0 * (a.y + p.y) + w1 * (b.y + q.y);
    rr.z = w0 * (a.z + p.z) + w1 * (b.z + q.z);
    rr.w = w0 * (a.w + p.w) + w1 * (b.w + q.w);
    o[h] = rr;
}

// ---------------- launch ----------------
extern "C" void kernel_launch(void* const* d_in, const int* in_sizes, int n_in,
                              void* d_out, int out_size) {
    const float* x  = (const float*)d_in[0];
    const float* Wg = (const float*)d_in[1];
    const float* W1 = (const float*)d_in[2];
    const float* b1 = (const float*)d_in[3];
    const float* W2 = (const float*)d_in[4];
    const float* b2 = (const float*)d_in[5];
    float* out = (float*)d_out;

    cudaFuncSetAttribute(gemm_tc<0>, cudaFuncAttributeMaxDynamicSharedMemorySize, SMEM_BYTES);
    cudaFuncSetAttribute(gemm_tc<1>, cudaFuncAttributeMaxDynamicSharedMemorySize, SMEM_BYTES);

    // Device addresses of __device__ symbols (host symbol names are not device ptrs)
    __half* xh  = nullptr; cudaGetSymbolAddress((void**)&xh,  g_xh);
    __half* w1h = nullptr; cudaGetSymbolAddress((void**)&w1h, g_w1h);
    __half* w2h = nullptr; cudaGetSymbolAddress((void**)&w2h, g_w2h);
    __half* hdn = nullptr; cudaGetSymbolAddress((void**)&hdn, g_hdn);

    // Launch order chosen so the 4th launch (= ncu capture slot) is gemm_up.
    conv3_kernel<<<8192, 256>>>(                          // 1 (also zeroes g_counts)
        (const float4*)x,  (h4*)xh,  NT * HD / 4,
        (const float4*)W1, (h4*)w1h, NE * HD * ID / 4,
        (const float4*)W2, (h4*)w2h, NE * ID * HD / 4);
    gate_kernel<<<NT / 8, 256>>>(x, Wg);                  // 2
    prefix_kernel<<<1, 32>>>();                           // 3
    gemm_tc<0><<<dim3(NE * RTILES, ID / TN), 256, SMEM_BYTES>>>(xh,  w1h, b1);  // 4 <- profiled
    gemm_tc<1><<<dim3(NE * RTILES, HD / TN), 256, SMEM_BYTES>>>(hdn, w2h, b1);  // 5
    combine_kernel<<<NT, 256>>>(b2, out);                 // 6
}

// round 16
// speedup vs baseline: 1.1541x; 1.1541x over previous
#include <cuda_runtime.h>
#include <cuda_fp16.h>
#include <mma.h>
#include <cstdint>
#include <math.h>

using namespace nvcuda;

// Problem constants (B=2, S=2048, H=1024, E=8, I=4096, top-2)
#define NT 4096
#define HD 1024
#define NE 8
#define ID 4096
#define NSLOT (2 * NT)

// GEMM tiling: CTA 128x128, 8 warps, warp 32x64, BK=32 (fp16), 4-stage cp.async
// (identical to the 658us R14 configuration)
#define TM 128
#define TN 128
#define BK 32
#define LDA 40            // As leading dim (halfs); row stride 80B
#define LDB 136           // Bs leading dim (halfs); row stride 272B
#define RTILES 32         // NT / TM

#define ASZ (TM * LDA)            // 5120 halfs
#define BSZ (BK * LDB)            // 4352 halfs
#define STAGE_H (ASZ + BSZ)       // 9472 halfs
#define STAGE_B (STAGE_H * 2)     // 18944 bytes
#define ASZB (ASZ * 2)            // 10240 bytes
#define NSTAGE 4
#define SMEM_BYTES (NSTAGE * STAGE_B)   // 75776

// ---------------- static device scratch (no runtime alloc) ----------------
__device__ int    g_counts[NE];
__device__ int    g_offsets[NE + 1];
__device__ int    g_tok[NE * NT];
__device__ int    g_meta_i[NT * 4];
__device__ float  g_meta_w[NT * 2];
__device__ __half g_hdn[(size_t)NSLOT * ID];   // fp16 silu(x@W1) rows (compacted)
__device__ float  g_y[(size_t)NSLOT * HD];
// fp16 operand copies
__device__ __half g_xh[(size_t)NT * HD];
__device__ __half g_w1h[(size_t)NE * HD * ID];
__device__ __half g_w2h[(size_t)NE * ID * HD];

// ---------------- helpers ----------------
__device__ __forceinline__ uint32_t smem_u32(const void* p) {
    uint32_t a;
    asm("{ .reg .u64 t; cvta.to.shared.u64 t, %1; cvt.u32.u64 %0, t; }" : "=r"(a) : "l"(p));
    return a;
}
// 16B async copy; bytes==0 -> zero-fill destination
__device__ __forceinline__ void cp16(uint32_t dst, const void* src, uint32_t bytes) {
    asm volatile("cp.async.cg.shared.global [%0], [%1], 16, %2;"
                 :: "r"(dst), "l"(src), "r"(bytes) : "memory");
}
#define CP_COMMIT() asm volatile("cp.async.commit_group;" ::: "memory")

struct __align__(8) h4 { __half2 a, b; };

// ---------------- gate / prefix ----------------
__global__ void gate_kernel(const float* __restrict__ x, const float* __restrict__ Wg) {
    int warp = (blockIdx.x * blockDim.x + threadIdx.x) >> 5;
    int lane = threadIdx.x & 31;
    if (warp >= NT) return;
    const float* xr = x + (size_t)warp * HD;

    float acc[NE];
#pragma unroll
    for (int i = 0; i < NE; i++) acc[i] = 0.f;
    for (int j = lane; j < HD; j += 32) {
        float xv = xr[j];
        const float4* w4 = reinterpret_cast<const float4*>(Wg + j * NE);
        float4 wa = w4[0], wb = w4[1];
        acc[0] += xv * wa.x; acc[1] += xv * wa.y;
        acc[2] += xv * wa.z; acc[3] += xv * wa.w;
        acc[4] += xv * wb.x; acc[5] += xv * wb.y;
        acc[6] += xv * wb.z; acc[7] += xv * wb.w;
    }
#pragma unroll
    for (int i = 0; i < NE; i++) {
#pragma unroll
        for (int o = 16; o > 0; o >>= 1)
            acc[i] += __shfl_xor_sync(0xffffffffu, acc[i], o);
    }
    if (lane == 0) {
        int i0 = 0; float m0 = acc[0];
#pragma unroll
        for (int i = 1; i < NE; i++) if (acc[i] > m0) { m0 = acc[i]; i0 = i; }
        int i1 = -1; float m1 = -1e30f;
#pragma unroll
        for (int i = 0; i < NE; i++)
            if (i != i0 && acc[i] > m1) { m1 = acc[i]; i1 = i; }
        float w0 = 1.f / (1.f + expf(m1 - m0));
        float w1 = 1.f - w0;
        int s0 = atomicAdd(&g_counts[i0], 1);
        int s1 = atomicAdd(&g_counts[i1], 1);
        g_tok[i0 * NT + s0] = warp;
        g_tok[i1 * NT + s1] = warp;
        g_meta_i[warp * 4 + 0] = i0;
        g_meta_i[warp * 4 + 1] = s0;
        g_meta_i[warp * 4 + 2] = i1;
        g_meta_i[warp * 4 + 3] = s1;
        g_meta_w[warp * 2 + 0] = w0;
        g_meta_w[warp * 2 + 1] = w1;
    }
}

__global__ void prefix_kernel() {
    if (threadIdx.x == 0) {
        int s = 0;
        g_offsets[0] = 0;
        for (int e = 0; e < NE; e++) { s += g_counts[e]; g_offsets[e + 1] = s; }
    }
}

// ---------------- fused reset + fp32->fp16 convert (x, W1, W2) ----------------
// Runs FIRST; gate (which atomics g_counts) launches after it in stream order.
__global__ void conv3_kernel(const float4* __restrict__ s0, h4* __restrict__ d0, int n0,
                             const float4* __restrict__ s1, h4* __restrict__ d1, int n1,
                             const float4* __restrict__ s2, h4* __restrict__ d2, int n2)
{
    if (blockIdx.x == 0 && threadIdx.x < NE) g_counts[threadIdx.x] = 0;

    int total = n0 + n1 + n2;
    int stride = gridDim.x * blockDim.x;
    for (int i = blockIdx.x * blockDim.x + threadIdx.x; i < total; i += stride) {
        if (i < n0) {
            float4 v = s0[i];
            h4 o; o.a = __floats2half2_rn(v.x, v.y); o.b = __floats2half2_rn(v.z, v.w);
            d0[i] = o;
        } else if (i < n0 + n1) {
            int k = i - n0;
            float4 v = s1[k];
            h4 o; o.a = __floats2half2_rn(v.x, v.y); o.b = __floats2half2_rn(v.z, v.w);
            d1[k] = o;
        } else {
            int k = i - n0 - n1;
            float4 v = s2[k];
            h4 o; o.a = __floats2half2_rn(v.x, v.y); o.b = __floats2half2_rn(v.z, v.w);
            d2[k] = o;
        }
    }
}

// ---------------- grouped GEMM (MODE 0 = up+SiLU, 1 = down), fp16 MMA ----------------
template <int MODE>
__global__ __launch_bounds__(256, 2) void gemm_tc(
    const __half* __restrict__ A, const __half* __restrict__ W,
    const float* __restrict__ bias)
{
    extern __shared__ __align__(16) char smem[];
    __half* sh = reinterpret_cast<__half*>(smem);
    const int KS  = (MODE == 0) ? HD : ID;   // K extent (A row length)
    const int NSW = (MODE == 0) ? ID : HD;   // W row length (N extent)
    const int KT  = KS / BK;                 // 32 (up) / 128 (down)

    int e  = blockIdx.x / RTILES;
    int rt = blockIdx.x % RTILES;
    int n_e = g_counts[e];
    int row0 = rt * TM;
    if (row0 >= n_e) return;
    int n0 = blockIdx.y * TN;
    int tid = threadIdx.x;
    uint32_t sb = smem_u32(sh);

    // A staging: 2 threads per row; each stages 32B (16 halfs) of the 64B row
    const __half* aptr = nullptr;
    {
        int gs = row0 + (tid >> 1);
        if (gs < n_e) {
            if (MODE == 0) aptr = A + (size_t)g_tok[e * NT + gs] * HD;
            else           aptr = A + (size_t)(g_offsets[e] + gs) * ID;
        }
    }
    int ahalf = tid & 1;
    uint32_t a_dst = sb + (tid >> 1) * 80 + ahalf * 32;
    uint32_t avalid = aptr ? 16u : 0u;
    const __half* adummy = W;

    // B staging: 8 threads per row (32 rows); each stages 32B of the 256B row
    int brow = tid >> 3, bseg = tid & 7;
    const __half* wbase = W + (size_t)e * HD * ID
                            + (size_t)brow * NSW + n0 + bseg * 16;
    uint32_t b_dst = sb + ASZB + brow * 272 + bseg * 32;

    auto issue = [&](int kt) {
        uint32_t so = (uint32_t)((kt & (NSTAGE - 1)) * STAGE_B);
        int k0 = kt * BK;
        const __half* as = aptr ? (aptr + k0 + ahalf * 16) : adummy;
        cp16(a_dst + so,      as,     avalid);
        cp16(a_dst + so + 16, as + 8, avalid);
        const __half* bs = wbase + (size_t)k0 * NSW;
        cp16(b_dst + so,      bs,     16u);
        cp16(b_dst + so + 16, bs + 8, 16u);
        CP_COMMIT();
    };

    int wrp = tid >> 5, wm = wrp >> 1, wn = wrp & 1, lane = tid & 31;

    wmma::fragment<wmma::accumulator, 16, 16, 16, float> c[2][4];
#pragma unroll
    for (int i = 0; i < 2; i++)
#pragma unroll
        for (int j = 0; j < 4; j++) wmma::fill_fragment(c[i][j], 0.f);

    issue(0);
    if (KT > 1) issue(1);
    if (KT > 2) issue(2);

    for (int kt = 0; kt < KT; ++kt) {
        if (kt + 2 < KT)      asm volatile("cp.async.wait_group 2;" ::: "memory");
        else if (kt + 1 < KT) asm volatile("cp.async.wait_group 1;" ::: "memory");
        else                  asm volatile("cp.async.wait_group 0;" ::: "memory");
        __syncthreads();                 // stage kt visible; stage (kt+3)%4 readers retired
        if (kt + 3 < KT) issue(kt + 3);

        const __half* As = sh + (size_t)(kt & (NSTAGE - 1)) * STAGE_H;
        const __half* Bs = As + ASZ;
#pragma unroll
        for (int kk = 0; kk < 2; ++kk) {    // two k16 steps per BK=32 slice
            wmma::fragment<wmma::matrix_a, 16, 16, 16, half, wmma::row_major> af[2];
            wmma::fragment<wmma::matrix_b, 16, 16, 16, half, wmma::row_major> bf[4];
#pragma unroll
            for (int i = 0; i < 2; i++)
                wmma::load_matrix_sync(af[i], &As[(wm * 32 + i * 16) * LDA + kk * 16], LDA);
#pragma unroll
            for (int j = 0; j < 4; j++)
                wmma::load_matrix_sync(bf[j], &Bs[(kk * 16) * LDB + wn * 64 + j * 16], LDB);
#pragma unroll
            for (int i = 0; i < 2; i++)
#pragma unroll
                for (int j = 0; j < 4; j++)
                    wmma::mma_sync(c[i][j], af[i], bf[j], c[i][j]);
        }
    }
    __syncthreads();   // all MMAs done; stage smem reusable as epilogue patch

    int base_row = g_offsets[e] + row0;
    float* patch = reinterpret_cast<float*>(smem) + wrp * 320;   // 16x20 floats per warp
#pragma unroll
    for (int i = 0; i < 2; i++) {
#pragma unroll
        for (int j = 0; j < 4; j++) {
            wmma::store_matrix_sync(patch, c[i][j], 20, wmma::mem_row_major);
            __syncwarp();
            int lrb = wm * 32 + i * 16;
            int lcb = wn * 64 + j * 16;
#pragma unroll
            for (int q = 0; q < 8; q++) {
                int el = lane + q * 32;
                int r = el >> 4, cc = el & 15;
                int lr = lrb + r;
                if (row0 + lr < n_e) {
                    int gc = n0 + lcb + cc;
                    if (MODE == 0) {
                        float v = patch[r * 20 + cc] + bias[(size_t)e * ID + gc];
                        float sv = v / (1.f + expf(-v));
                        g_hdn[(size_t)(base_row + lr) * ID + gc] = __float2half_rn(sv);
                    } else {
                        g_y[(size_t)(base_row + lr) * HD + gc] = patch[r * 20 + cc];
                    }
                }
            }
            __syncwarp();
        }
    }
}

// ---------------- deterministic per-token combine ----------------
__global__ void combine_kernel(const float* __restrict__ b2, float* __restrict__ out) {
    int t = blockIdx.x;
    int e0 = g_meta_i[t * 4 + 0], s0 = g_meta_i[t * 4 + 1];
    int e1 = g_meta_i[t * 4 + 2], s1 = g_meta_i[t * 4 + 3];
    float w0 = g_meta_w[t * 2 + 0];
    float w1 = g_meta_w[t * 2 + 1];
    int r0 = g_offsets[e0] + s0;
    int r1 = g_offsets[e1] + s1;

    const float4* y0 = reinterpret_cast<const float4*>(g_y + (size_t)r0 * HD);
    const float4* y1 = reinterpret_cast<const float4*>(g_y + (size_t)r1 * HD);
    const float4* c0 = reinterpret_cast<const float4*>(b2 + (size_t)e0 * HD);
    const float4* c1 = reinterpret_cast<const float4*>(b2 + (size_t)e1 * HD);
    float4* o = reinterpret_cast<float4*>(out + (size_t)t * HD);

    int h = threadIdx.x;  // blockDim = 256 == HD/4
    float4 a = y0[h], b = y1[h], p = c0[h], q = c1[h];
    float4 rr;
    rr.x = w0 * (a.x + p.x) + w1 * (b.x + q.x);
    rr.y = w0 * (a.y + p.y) + w1 * (b.y + q.y);
    rr.z = w0 * (a.z + p.z) + w1 * (b.z + q.z);
    rr.w = w0 * (a.w + p.w) + w1 * (b.w + q.w);
    o[h] = rr;
}

// ---------------- launch ----------------
extern "C" void kernel_launch(void* const* d_in, const int* in_sizes, int n_in,
                              void* d_out, int out_size) {
    const float* x  = (const float*)d_in[0];
    const float* Wg = (const float*)d_in[1];
    const float* W1 = (const float*)d_in[2];
    const float* b1 = (const float*)d_in[3];
    const float* W2 = (const float*)d_in[4];
    const float* b2 = (const float*)d_in[5];
    float* out = (float*)d_out;

    cudaFuncSetAttribute(gemm_tc<0>, cudaFuncAttributeMaxDynamicSharedMemorySize, SMEM_BYTES);
    cudaFuncSetAttribute(gemm_tc<1>, cudaFuncAttributeMaxDynamicSharedMemorySize, SMEM_BYTES);

    // Device addresses of __device__ symbols (host symbol names are not device ptrs)
    __half* xh  = nullptr; cudaGetSymbolAddress((void**)&xh,  g_xh);
    __half* w1h = nullptr; cudaGetSymbolAddress((void**)&w1h, g_w1h);
    __half* w2h = nullptr; cudaGetSymbolAddress((void**)&w2h, g_w2h);
    __half* hdn = nullptr; cudaGetSymbolAddress((void**)&hdn, g_hdn);

    // Launch order chosen so the 4th launch (= ncu capture slot) is gemm_up.
    conv3_kernel<<<8192, 256>>>(                          // 1 (also zeroes g_counts)
        (const float4*)x,  (h4*)xh,  NT * HD / 4,
        (const float4*)W1, (h4*)w1h, NE * HD * ID / 4,
        (const float4*)W2, (h4*)w2h, NE * ID * HD / 4);
    gate_kernel<<<NT / 8, 256>>>(x, Wg);                  // 2
    prefix_kernel<<<1, 32>>>();                           // 3
    gemm_tc<0><<<dim3(NE * RTILES, ID / TN), 256, SMEM_BYTES>>>(xh,  w1h, b1);  // 4 <- profiled
    gemm_tc<1><<<dim3(NE * RTILES, HD / TN), 256, SMEM_BYTES>>>(hdn, w2h, b1);  // 5
    combine_kernel<<<NT, 256>>>(b2, out);                 // 6
}